// round 4
// baseline (speedup 1.0000x reference)
#include <cuda_runtime.h>

// LayerwiseLowRankUplift: out = z + U_l (V_l^T z), per-sample layer l.
// B=2048, H=2048, R=64, L=32 (derived at runtime from in_sizes).
//
// Strategy:
//  1) Group samples by layer (setup kernel) so each compute CTA amortizes the
//     1MB of (u,v) weights over 16 samples (2GB -> 160MB of L2 traffic).
//  2) Two-phase fused register-blocked GEMM, with packed f32x2 FMA
//     (PTX fma.rn.f32x2 -> SASS FFMA2) to halve the FMA issue count.

#define T_SAMP   16
#define KT       64
#define RANK     64
#define L_CAP    64
#define B_CAP    4096
#define MAX_TILES 512

__device__ int g_order[B_CAP];
__device__ int g_tile_layer[MAX_TILES];
__device__ int g_tile_start[MAX_TILES];
__device__ int g_tile_cnt[MAX_TILES];
__device__ int g_num_tiles;

typedef unsigned long long u64t;

__device__ __forceinline__ u64t pack2(float lo, float hi) {
    u64t d;
    asm("mov.b64 %0, {%1, %2};" : "=l"(d) : "f"(lo), "f"(hi));
    return d;
}
__device__ __forceinline__ float2 unpack2(u64t p) {
    float2 r;
    asm("mov.b64 {%0, %1}, %2;" : "=f"(r.x), "=f"(r.y) : "l"(p));
    return r;
}
// Packed dual-FMA: d.lo = a.lo*b.lo+c.lo ; d.hi = a.hi*b.hi+c.hi  (FFMA2)
__device__ __forceinline__ u64t ffma2(u64t a, u64t b, u64t c) {
    u64t d;
    asm("fma.rn.f32x2 %0, %1, %2, %3;" : "=l"(d) : "l"(a), "l"(b), "l"(c));
    return d;
}

// ---------------------------------------------------------------------------
// Setup: histogram layer_ids, prefix-sum, scatter sample ids into layer-sorted
// order, and emit a worklist of (layer, start, count<=16) tiles. Single CTA.
// ---------------------------------------------------------------------------
__global__ void llru_setup_kernel(const int* __restrict__ lids, int B, int L)
{
    __shared__ int cnt[L_CAP];
    __shared__ int cur[L_CAP];
    int tid = threadIdx.x;

    for (int i = tid; i < L_CAP; i += blockDim.x) cnt[i] = 0;
    __syncthreads();

    for (int b = tid; b < B; b += blockDim.x)
        atomicAdd(&cnt[lids[b]], 1);
    __syncthreads();

    if (tid == 0) {
        int acc = 0;
        int nt = 0;
        for (int l = 0; l < L; l++) {
            cur[l] = acc;
            int c = cnt[l];
            for (int t = 0; t < c; t += T_SAMP) {
                g_tile_layer[nt] = l;
                g_tile_start[nt] = acc + t;
                g_tile_cnt[nt]   = min(T_SAMP, c - t);
                nt++;
            }
            acc += c;
        }
        g_num_tiles = nt;
    }
    __syncthreads();

    for (int b = tid; b < B; b += blockDim.x) {
        int p = atomicAdd(&cur[lids[b]], 1);
        g_order[p] = b;
    }
}

// ---------------------------------------------------------------------------
// Compute: one CTA = up to 16 samples sharing one layer. 256 threads.
// Phase 1: proj[16][64] = Z_tile[16,H] @ V_l[H,64]   (k-tiled, KT=64)
// Phase 2: out = z + proj[16,64] @ U_l[H,64]^T       (h-tiled, HT=64)
// Thread owns lane r = tid&63 (rank lane / h lane) and 4 samples (tid>>6).
// All inner-loop FMAs are packed f32x2.
// ---------------------------------------------------------------------------
__global__ void __launch_bounds__(256)
llru_compute_kernel(const float* __restrict__ z,
                    const float* __restrict__ u,
                    const float* __restrict__ v,
                    float* __restrict__ out,
                    int H)
{
    int g = blockIdx.x;
    if (g >= g_num_tiles) return;

    const int layer = g_tile_layer[g];
    const int start = g_tile_start[g];
    const int cnt   = g_tile_cnt[g];

    const int tid = threadIdx.x;
    const int r   = tid & 63;          // rank lane / h lane within tile
    const int sq  = tid >> 6;          // sample quad (0..3)

    __shared__ int   sid[T_SAMP];
    __shared__ __align__(16) float Zs[T_SAMP][KT];       // 4KB
    __shared__ __align__(16) float Vs[KT][RANK];         // 16KB
    __shared__ __align__(16) float Us[KT][RANK + 4];     // 17KB, stride 68 floats
                                                         //  = 272B == 16B shift mod 128B
    __shared__ __align__(16) float projS[T_SAMP][RANK];  // 4KB

    if (tid < T_SAMP)
        sid[tid] = (tid < cnt) ? g_order[start + tid] : g_order[start];
    __syncthreads();

    const size_t wbase = (size_t)layer * H * RANK;
    const float* vL = v + wbase;
    const float* uL = u + wbase;

    // ---------------- Phase 1: proj = Z @ V ----------------
    u64t accp[4] = {0ull, 0ull, 0ull, 0ull};   // packed (even-k, odd-k) partials

    for (int k0 = 0; k0 < H; k0 += KT) {
        // Z tile: 16x64 floats = 256 float4, one per thread.
        {
            int srow = tid >> 4;           // 0..15
            int c4   = (tid & 15) << 2;    // 0..60
            float4 zz = *(const float4*)(z + (size_t)sid[srow] * H + k0 + c4);
            *(float4*)&Zs[srow][c4] = zz;
        }
        // V tile: 64x64 floats = 1024 float4, 4 per thread.
        #pragma unroll
        for (int j = 0; j < 4; j++) {
            int idx = tid + j * 256;
            int krow = idx >> 4;
            int c4   = (idx & 15) << 2;
            float4 vv = *(const float4*)(vL + (size_t)(k0 + krow) * RANK + c4);
            *(float4*)&Vs[krow][c4] = vv;
        }
        __syncthreads();

        #pragma unroll
        for (int k = 0; k < KT; k += 4) {
            u64t vp01 = pack2(Vs[k + 0][r], Vs[k + 1][r]);
            u64t vp23 = pack2(Vs[k + 2][r], Vs[k + 3][r]);
            #pragma unroll
            for (int i = 0; i < 4; i++) {
                ulonglong2 zz = *(const ulonglong2*)&Zs[sq * 4 + i][k];
                accp[i] = ffma2(zz.x, vp01, accp[i]);
                accp[i] = ffma2(zz.y, vp23, accp[i]);
            }
        }
        __syncthreads();
    }

    // proj -> smem (reduce packed halves)
    #pragma unroll
    for (int i = 0; i < 4; i++) {
        float2 a = unpack2(accp[i]);
        projS[sq * 4 + i][r] = a.x + a.y;
    }
    __syncthreads();

    // ---------------- Phase 2: out = z + proj @ U^T ----------------
    for (int h0 = 0; h0 < H; h0 += KT) {
        // U tile: 64 rows x 64 floats into stride-68 smem (conflict-free .128).
        #pragma unroll
        for (int j = 0; j < 4; j++) {
            int idx = tid + j * 256;
            int hrow = idx >> 4;
            int c4   = (idx & 15) << 2;
            float4 uu = *(const float4*)(uL + (size_t)(h0 + hrow) * RANK + c4);
            *(float4*)&Us[hrow][c4] = uu;
        }
        __syncthreads();

        u64t acc2p[4] = {0ull, 0ull, 0ull, 0ull};
        #pragma unroll
        for (int r4 = 0; r4 < RANK; r4 += 4) {
            ulonglong2 uu = *(const ulonglong2*)&Us[r][r4];
            #pragma unroll
            for (int i = 0; i < 4; i++) {
                ulonglong2 pp = *(const ulonglong2*)&projS[sq * 4 + i][r4];
                acc2p[i] = ffma2(pp.x, uu.x, acc2p[i]);
                acc2p[i] = ffma2(pp.y, uu.y, acc2p[i]);
            }
        }

        #pragma unroll
        for (int i = 0; i < 4; i++) {
            int s = sq * 4 + i;
            if (s < cnt) {
                float2 a = unpack2(acc2p[i]);
                size_t gidx = (size_t)sid[s] * H + h0 + r;
                out[gidx] = z[gidx] + (a.x + a.y);
            }
        }
        __syncthreads();
    }
}

extern "C" void kernel_launch(void* const* d_in, const int* in_sizes, int n_in,
                              void* d_out, int out_size)
{
    const float* z    = (const float*)d_in[0];
    const int*   lids = (const int*)d_in[1];
    const float* u    = (const float*)d_in[2];
    const float* v    = (const float*)d_in[3];
    float*       out  = (float*)d_out;

    int B = in_sizes[1];
    int H = in_sizes[0] / B;
    int L = in_sizes[2] / (H * RANK);
    if (L < 1) L = 1;
    if (L > L_CAP) L = L_CAP;

    llru_setup_kernel<<<1, 256>>>(lids, B, L);

    int ntiles = B / T_SAMP + L;   // upper bound on emitted tiles
    if (ntiles > MAX_TILES) ntiles = MAX_TILES;
    llru_compute_kernel<<<ntiles, 256>>>(z, u, v, out, H);
}

// round 7
// speedup vs baseline: 1.1969x; 1.1969x over previous
#include <cuda_runtime.h>

// LayerwiseLowRankUplift: out = z + U_l (V_l^T z), per-sample layer l.
// B=2048, H=2048, R=64, L=32.
//
// R5: software-pipelined (cp.async double-buffer) fused kernel.
//  - Samples grouped by layer (setup kernel): 16 samples/CTA amortize 1MB
//    of (u,v) -> ~145MB total L2 traffic.
//  - Unified 64-tile pipeline: 32 V+Z tiles (phase 1) then 32 U+Z tiles
//    (phase 2); phase-2 prefetch overlaps the last phase-1 computes.
//  - Packed f32x2 FMA (FFMA2) halves FMA issue count.

#define T_SAMP   16
#define KT       64
#define RANK     64
#define L_CAP    64
#define B_CAP    4096
#define MAX_TILES 512

#define NSTAGE   2
// stage float layout:
//  phase1: V[64][64] at [0,4096), Z[16][64] at [4096,5120)
//  phase2: U[64][68] at [0,4352), Z[16][64] at [4352,5376)
#define STAGE_F  5376

__device__ int g_order[B_CAP];
__device__ int g_tile_layer[MAX_TILES];
__device__ int g_tile_start[MAX_TILES];
__device__ int g_tile_cnt[MAX_TILES];
__device__ int g_num_tiles;

typedef unsigned long long u64t;

__device__ __forceinline__ u64t pack2(float lo, float hi) {
    u64t d;
    asm("mov.b64 %0, {%1, %2};" : "=l"(d) : "f"(lo), "f"(hi));
    return d;
}
__device__ __forceinline__ float2 unpack2(u64t p) {
    float2 r;
    asm("mov.b64 {%0, %1}, %2;" : "=f"(r.x), "=f"(r.y) : "l"(p));
    return r;
}
__device__ __forceinline__ u64t ffma2(u64t a, u64t b, u64t c) {
    u64t d;
    asm("fma.rn.f32x2 %0, %1, %2, %3;" : "=l"(d) : "l"(a), "l"(b), "l"(c));
    return d;
}
__device__ __forceinline__ void cp16(float* sdst, const float* gsrc) {
    unsigned s = (unsigned)__cvta_generic_to_shared(sdst);
    asm volatile("cp.async.cg.shared.global [%0], [%1], 16;" :: "r"(s), "l"(gsrc));
}
__device__ __forceinline__ void cp_commit() {
    asm volatile("cp.async.commit_group;");
}
__device__ __forceinline__ void cp_wait1() {
    asm volatile("cp.async.wait_group 1;");
}

// ---------------------------------------------------------------------------
// Setup: histogram layer_ids, prefix-sum, scatter sample ids into layer-sorted
// order, and emit a worklist of (layer, start, count<=16) tiles. Single CTA.
// ---------------------------------------------------------------------------
__global__ void llru_setup_kernel(const int* __restrict__ lids, int B, int L)
{
    __shared__ int cnt[L_CAP];
    __shared__ int cur[L_CAP];
    int tid = threadIdx.x;

    for (int i = tid; i < L_CAP; i += blockDim.x) cnt[i] = 0;
    __syncthreads();

    for (int b = tid; b < B; b += blockDim.x)
        atomicAdd(&cnt[lids[b]], 1);
    __syncthreads();

    if (tid == 0) {
        int acc = 0;
        int nt = 0;
        for (int l = 0; l < L; l++) {
            cur[l] = acc;
            int c = cnt[l];
            for (int t = 0; t < c; t += T_SAMP) {
                g_tile_layer[nt] = l;
                g_tile_start[nt] = acc + t;
                g_tile_cnt[nt]   = min(T_SAMP, c - t);
                nt++;
            }
            acc += c;
        }
        g_num_tiles = nt;
    }
    __syncthreads();

    for (int b = tid; b < B; b += blockDim.x) {
        int p = atomicAdd(&cur[lids[b]], 1);
        g_order[p] = b;
    }
}

// ---------------------------------------------------------------------------
// Compute: one CTA = up to 16 samples sharing one layer, 256 threads.
// Unified pipeline over 64 tiles:
//   t in [0,32):  proj += Z_tile(k) @ V_l(k)        (accumulate in regs)
//   t in [32,64): out = z + proj @ U_l(h)^T         (epilogue per tile)
// Thread owns lane r = tid&63 and 4 samples (quad sq = tid>>6).
// ---------------------------------------------------------------------------
__global__ void __launch_bounds__(256)
llru_compute_kernel(const float* __restrict__ z,
                    const float* __restrict__ u,
                    const float* __restrict__ v,
                    float* __restrict__ out,
                    int H)
{
    int g = blockIdx.x;
    if (g >= g_num_tiles) return;

    const int layer = g_tile_layer[g];
    const int start = g_tile_start[g];
    const int cnt   = g_tile_cnt[g];

    const int tid = threadIdx.x;
    const int r   = tid & 63;
    const int sq  = tid >> 6;

    __shared__ int sid[T_SAMP];
    __shared__ __align__(16) float stage[NSTAGE][STAGE_F];   // 43008 B
    __shared__ __align__(16) float projS[T_SAMP][RANK];      //  4096 B

    if (tid < T_SAMP)
        sid[tid] = (tid < cnt) ? g_order[start + tid] : g_order[start];
    __syncthreads();

    const size_t wbase = (size_t)layer * H * RANK;
    const float* vL = v + wbase;
    const float* uL = u + wbase;

    const int NT1 = H / KT;        // 32 phase-1 tiles
    const int NT  = 2 * NT1;       // 64 total

    // per-thread load coordinates (same for every tile)
    const int srow = tid >> 4;               // 0..15  (z row)
    const int zc4  = (tid & 15) << 2;        // 0..60  (z col quad)
    const float* zrow = z + (size_t)sid[srow] * H + zc4;

    // ---- tile issue (5 cp.async per thread, one commit group) ----
    auto issue_tile = [&](int t) {
        float* buf = stage[t & 1];
        if (t < NT1) {
            int k0 = t * KT;
            #pragma unroll
            for (int j = 0; j < 4; j++) {
                int idx  = tid + j * 256;
                int krow = idx >> 4;
                int c4   = (idx & 15) << 2;
                cp16(buf + krow * 64 + c4,
                     vL + (size_t)(k0 + krow) * RANK + c4);
            }
            cp16(buf + 4096 + srow * 64 + zc4, zrow + k0);
        } else {
            int h0 = (t - NT1) * KT;
            #pragma unroll
            for (int j = 0; j < 4; j++) {
                int idx  = tid + j * 256;
                int hrow = idx >> 4;
                int c4   = (idx & 15) << 2;
                cp16(buf + hrow * 68 + c4,                // stride 68: LDS.128-safe
                     uL + (size_t)(h0 + hrow) * RANK + c4);
            }
            cp16(buf + 4352 + srow * 64 + zc4, zrow + h0);
        }
        cp_commit();
    };

    // prologue: tiles 0 and 1 in flight
    issue_tile(0);
    issue_tile(1);

    u64t accp[4] = {0ull, 0ull, 0ull, 0ull};   // phase-1 packed partials

    for (int t = 0; t < NT; t++) {
        cp_wait1();          // tile t landed (tile t+1 may still be in flight)
        __syncthreads();

        const float* buf = stage[t & 1];

        if (t < NT1) {
            // -------- phase 1: proj += Z @ V --------
            const float* Vb = buf;
            const float* Zb = buf + 4096;
            #pragma unroll
            for (int k = 0; k < KT; k += 4) {
                u64t vp01 = pack2(Vb[(k + 0) * 64 + r], Vb[(k + 1) * 64 + r]);
                u64t vp23 = pack2(Vb[(k + 2) * 64 + r], Vb[(k + 3) * 64 + r]);
                #pragma unroll
                for (int i = 0; i < 4; i++) {
                    ulonglong2 zz = *(const ulonglong2*)&Zb[(sq * 4 + i) * 64 + k];
                    accp[i] = ffma2(zz.x, vp01, accp[i]);
                    accp[i] = ffma2(zz.y, vp23, accp[i]);
                }
            }
            if (t == NT1 - 1) {
                #pragma unroll
                for (int i = 0; i < 4; i++) {
                    float2 a = unpack2(accp[i]);
                    projS[sq * 4 + i][r] = a.x + a.y;
                }
                // post-compute __syncthreads below publishes projS
            }
        } else {
            // -------- phase 2: out = z + proj @ U^T --------
            const int h0 = (t - NT1) * KT;
            const float* Ub = buf;
            const float* Z2 = buf + 4352;

            u64t acc2p[4] = {0ull, 0ull, 0ull, 0ull};
            #pragma unroll
            for (int r4 = 0; r4 < RANK; r4 += 4) {
                ulonglong2 uu = *(const ulonglong2*)&Ub[r * 68 + r4];
                #pragma unroll
                for (int i = 0; i < 4; i++) {
                    ulonglong2 pp = *(const ulonglong2*)&projS[sq * 4 + i][r4];
                    acc2p[i] = ffma2(pp.x, uu.x, acc2p[i]);
                    acc2p[i] = ffma2(pp.y, uu.y, acc2p[i]);
                }
            }
            #pragma unroll
            for (int i = 0; i < 4; i++) {
                int s = sq * 4 + i;
                if (s < cnt) {
                    float2 a = unpack2(acc2p[i]);
                    out[(size_t)sid[s] * H + h0 + r] =
                        Z2[s * 64 + r] + (a.x + a.y);
                }
            }
        }

        __syncthreads();     // everyone done reading buf before it is refilled
        if (t + NSTAGE < NT) issue_tile(t + NSTAGE);
        else                 cp_commit();     // empty group keeps wait_group(1) exact
    }
}

extern "C" void kernel_launch(void* const* d_in, const int* in_sizes, int n_in,
                              void* d_out, int out_size)
{
    const float* z    = (const float*)d_in[0];
    const int*   lids = (const int*)d_in[1];
    const float* u    = (const float*)d_in[2];
    const float* v    = (const float*)d_in[3];
    float*       out  = (float*)d_out;

    int B = in_sizes[1];
    int H = in_sizes[0] / B;
    int L = in_sizes[2] / (H * RANK);
    if (L < 1) L = 1;
    if (L > L_CAP) L = L_CAP;

    llru_setup_kernel<<<1, 256>>>(lids, B, L);

    int ntiles = B / T_SAMP + L;   // upper bound on emitted tiles
    if (ntiles > MAX_TILES) ntiles = MAX_TILES;
    llru_compute_kernel<<<ntiles, 256>>>(z, u, v, out, H);
}

// round 8
// speedup vs baseline: 1.6434x; 1.3731x over previous
#include <cuda_runtime.h>
#include <cstdint>

// LayerwiseLowRankUplift: out = z + U_l (V_l^T z), per-sample layer l.
// B=2048, H=2048, R=64, L=32.
//
// R8: tensor-core (mma.sync m16n8k8 tf32) fused kernel.
//  - Samples grouped by layer (setup kernel): 16 samples/CTA.
//  - cp.async double-buffered pipeline over 64 tiles (32 V, 32 U).
//  - fp32 data fed directly as tf32 (no conversion pass); delta term is ~3.6%
//    of |out|, so tf32 rounding contributes ~5e-5 rel err overall.
//  - All smem tiles stride-68 floats: conflict-free mma fragment gathers.

#define T_SAMP   16
#define KT       64
#define RANK     64
#define L_CAP    64
#define B_CAP    4096
#define MAX_TILES 512

#define NSTAGE   2
#define VSTRIDE  68
// stage float layout:
//  phase1: V[64][68] at [0,4352), Z[16][68] at [4352,5440)
//  phase2: U[64][68] at [0,4352)
#define STAGE_F  5440

__device__ int g_order[B_CAP];
__device__ int g_tile_layer[MAX_TILES];
__device__ int g_tile_start[MAX_TILES];
__device__ int g_tile_cnt[MAX_TILES];
__device__ int g_num_tiles;

__device__ __forceinline__ void cp16(float* sdst, const float* gsrc) {
    unsigned s = (unsigned)__cvta_generic_to_shared(sdst);
    asm volatile("cp.async.cg.shared.global [%0], [%1], 16;" :: "r"(s), "l"(gsrc));
}
__device__ __forceinline__ void cp_commit() {
    asm volatile("cp.async.commit_group;");
}
__device__ __forceinline__ void cp_wait1() {
    asm volatile("cp.async.wait_group 1;");
}

// D += A(16x8, row) * B(8x8, col), tf32 inputs taken as raw fp32 bits.
__device__ __forceinline__ void mma_tf32(float* c,
                                         float a0, float a1, float a2, float a3,
                                         float b0, float b1)
{
    uint32_t ua0 = __float_as_uint(a0), ua1 = __float_as_uint(a1);
    uint32_t ua2 = __float_as_uint(a2), ua3 = __float_as_uint(a3);
    uint32_t ub0 = __float_as_uint(b0), ub1 = __float_as_uint(b1);
    asm volatile(
        "mma.sync.aligned.m16n8k8.row.col.f32.tf32.tf32.f32 "
        "{%0,%1,%2,%3}, {%4,%5,%6,%7}, {%8,%9}, {%0,%1,%2,%3};\n"
        : "+f"(c[0]), "+f"(c[1]), "+f"(c[2]), "+f"(c[3])
        : "r"(ua0), "r"(ua1), "r"(ua2), "r"(ua3), "r"(ub0), "r"(ub1));
}

// ---------------------------------------------------------------------------
// Setup: histogram layer_ids, prefix-sum, scatter sample ids into layer-sorted
// order, and emit a worklist of (layer, start, count<=16) tiles. Single CTA.
// ---------------------------------------------------------------------------
__global__ void llru_setup_kernel(const int* __restrict__ lids, int B, int L)
{
    __shared__ int cnt[L_CAP];
    __shared__ int cur[L_CAP];
    int tid = threadIdx.x;

    for (int i = tid; i < L_CAP; i += blockDim.x) cnt[i] = 0;
    __syncthreads();

    for (int b = tid; b < B; b += blockDim.x)
        atomicAdd(&cnt[lids[b]], 1);
    __syncthreads();

    if (tid == 0) {
        int acc = 0;
        int nt = 0;
        for (int l = 0; l < L; l++) {
            cur[l] = acc;
            int c = cnt[l];
            for (int t = 0; t < c; t += T_SAMP) {
                g_tile_layer[nt] = l;
                g_tile_start[nt] = acc + t;
                g_tile_cnt[nt]   = min(T_SAMP, c - t);
                nt++;
            }
            acc += c;
        }
        g_num_tiles = nt;
    }
    __syncthreads();

    for (int b = tid; b < B; b += blockDim.x) {
        int p = atomicAdd(&cur[lids[b]], 1);
        g_order[p] = b;
    }
}

// ---------------------------------------------------------------------------
// Compute: one CTA = up to 16 samples sharing one layer, 256 threads (8 warps).
// Unified 64-tile cp.async pipeline:
//   t in [0,32):  proj(frag) += Z_tile(k) @ V_l(k)      [mma, 2 acc chains]
//   t in [32,64): out = z + proj @ U_l(h)^T             [mma + epilogue]
// Warp w owns the 8-wide n-block [8w, 8w+8) of proj (phase1) / h-cols (phase2).
// ---------------------------------------------------------------------------
__global__ void __launch_bounds__(256)
llru_compute_kernel(const float* __restrict__ z,
                    const float* __restrict__ u,
                    const float* __restrict__ v,
                    float* __restrict__ out,
                    int H)
{
    int g = blockIdx.x;
    if (g >= g_num_tiles) return;

    const int layer = g_tile_layer[g];
    const int start = g_tile_start[g];
    const int cnt   = g_tile_cnt[g];

    const int tid  = threadIdx.x;
    const int lane = tid & 31;
    const int warp = tid >> 5;          // 0..7 -> n-block
    const int qr   = lane >> 2;         // 0..7
    const int qc   = lane & 3;          // 0..3

    __shared__ int sid[T_SAMP];
    __shared__ __align__(16) float stage[NSTAGE][STAGE_F];       // 43520 B
    __shared__ __align__(16) float projS[T_SAMP][VSTRIDE];       //  4352 B

    if (tid < T_SAMP)
        sid[tid] = (tid < cnt) ? g_order[start + tid] : g_order[start];
    __syncthreads();

    const size_t wbase = (size_t)layer * H * RANK;
    const float* vL = v + wbase;
    const float* uL = u + wbase;

    const int NT1 = H / KT;        // 32 phase-1 tiles
    const int NT  = 2 * NT1;       // 64 total

    // per-thread cp.async coordinates
    const int srow = tid >> 4;               // 0..15 (z row)
    const int zc4  = (tid & 15) << 2;        // 0..60
    const float* zrow = z + (size_t)sid[srow] * H + zc4;

    auto issue_tile = [&](int t) {
        float* buf = stage[t & 1];
        if (t < NT1) {
            int k0 = t * KT;
            #pragma unroll
            for (int j = 0; j < 4; j++) {
                int idx  = tid + j * 256;
                int krow = idx >> 4;
                int c4   = (idx & 15) << 2;
                cp16(buf + krow * VSTRIDE + c4,
                     vL + (size_t)(k0 + krow) * RANK + c4);
            }
            cp16(buf + 4352 + srow * VSTRIDE + zc4, zrow + k0);
        } else {
            int h0 = (t - NT1) * KT;
            #pragma unroll
            for (int j = 0; j < 4; j++) {
                int idx  = tid + j * 256;
                int hrow = idx >> 4;
                int c4   = (idx & 15) << 2;
                cp16(buf + hrow * VSTRIDE + c4,
                     uL + (size_t)(h0 + hrow) * RANK + c4);
            }
        }
        cp_commit();
    };

    issue_tile(0);
    issue_tile(1);

    // phase-1 accumulators: two chains to break HMMA dependency serialization
    float accA[4] = {0.f, 0.f, 0.f, 0.f};
    float accB[4] = {0.f, 0.f, 0.f, 0.f};
    // phase-2 A fragments (proj), loaded once at t == NT1
    float pa[8][4];

    for (int t = 0; t < NT; t++) {
        cp_wait1();
        __syncthreads();

        const float* buf = stage[t & 1];

        if (t < NT1) {
            // -------- phase 1: proj += Z @ V --------
            const float* Vb = buf;           // [64][68]
            const float* Zb = buf + 4352;    // [16][68]
            #pragma unroll
            for (int s = 0; s < 8; s++) {
                int k0 = s * 8;
                float a0 = Zb[qr * VSTRIDE + k0 + qc];
                float a1 = Zb[(qr + 8) * VSTRIDE + k0 + qc];
                float a2 = Zb[qr * VSTRIDE + k0 + qc + 4];
                float a3 = Zb[(qr + 8) * VSTRIDE + k0 + qc + 4];
                float b0 = Vb[(k0 + qc) * VSTRIDE + warp * 8 + qr];
                float b1 = Vb[(k0 + qc + 4) * VSTRIDE + warp * 8 + qr];
                if (s & 1) mma_tf32(accB, a0, a1, a2, a3, b0, b1);
                else       mma_tf32(accA, a0, a1, a2, a3, b0, b1);
            }
            if (t == NT1 - 1) {
                // publish proj: D frag layout c0:(qr, 2qc) c1:(qr, 2qc+1)
                //               c2:(qr+8, 2qc) c3:(qr+8, 2qc+1); n-block = warp*8
                int nb = warp * 8 + 2 * qc;
                projS[qr][nb]         = accA[0] + accB[0];
                projS[qr][nb + 1]     = accA[1] + accB[1];
                projS[qr + 8][nb]     = accA[2] + accB[2];
                projS[qr + 8][nb + 1] = accA[3] + accB[3];
                // trailing __syncthreads publishes projS
            }
        } else {
            if (t == NT1) {
                // load proj A-fragments once (k = rank dim, 8 steps of k8)
                #pragma unroll
                for (int s = 0; s < 8; s++) {
                    int k0 = s * 8;
                    pa[s][0] = projS[qr][k0 + qc];
                    pa[s][1] = projS[qr + 8][k0 + qc];
                    pa[s][2] = projS[qr][k0 + qc + 4];
                    pa[s][3] = projS[qr + 8][k0 + qc + 4];
                }
            }
            // -------- phase 2: out = z + proj @ U^T --------
            const int h0 = (t - NT1) * KT;
            const float* Ub = buf;           // [64][68], row = h, col = r

            float acc[4] = {0.f, 0.f, 0.f, 0.f};
            #pragma unroll
            for (int s = 0; s < 8; s++) {
                int k0 = s * 8;
                // B frag: (k = r = k0+qc(+4), n = h = warp*8 + qr)
                float b0 = Ub[(warp * 8 + qr) * VSTRIDE + k0 + qc];
                float b1 = Ub[(warp * 8 + qr) * VSTRIDE + k0 + qc + 4];
                mma_tf32(acc, pa[s][0], pa[s][1], pa[s][2], pa[s][3], b0, b1);
            }

            // epilogue: out[row][col] = z + acc ; D frag rows qr, qr+8,
            // cols h0 + warp*8 + 2qc + {0,1}
            int colbase = h0 + warp * 8 + 2 * qc;
            if (qr < cnt) {
                size_t gidx = (size_t)sid[qr] * H + colbase;
                float2 zz = *(const float2*)(z + gidx);
                float2 oo = make_float2(zz.x + acc[0], zz.y + acc[1]);
                *(float2*)(out + gidx) = oo;
            }
            if (qr + 8 < cnt) {
                size_t gidx = (size_t)sid[qr + 8] * H + colbase;
                float2 zz = *(const float2*)(z + gidx);
                float2 oo = make_float2(zz.x + acc[2], zz.y + acc[3]);
                *(float2*)(out + gidx) = oo;
            }
        }

        __syncthreads();
        if (t + NSTAGE < NT) issue_tile(t + NSTAGE);
        else                 cp_commit();   // keep wait_group(1) bookkeeping exact
    }
}

extern "C" void kernel_launch(void* const* d_in, const int* in_sizes, int n_in,
                              void* d_out, int out_size)
{
    const float* z    = (const float*)d_in[0];
    const int*   lids = (const int*)d_in[1];
    const float* u    = (const float*)d_in[2];
    const float* v    = (const float*)d_in[3];
    float*       out  = (float*)d_out;

    int B = in_sizes[1];
    int H = in_sizes[0] / B;
    int L = in_sizes[2] / (H * RANK);
    if (L < 1) L = 1;
    if (L > L_CAP) L = L_CAP;

    llru_setup_kernel<<<1, 256>>>(lids, B, L);

    int ntiles = B / T_SAMP + L;   // upper bound on emitted tiles
    if (ntiles > MAX_TILES) ntiles = MAX_TILES;
    llru_compute_kernel<<<ntiles, 256>>>(z, u, v, out, H);
}

// round 11
// speedup vs baseline: 1.9795x; 1.2045x over previous
#include <cuda_runtime.h>
#include <cstdint>

// LayerwiseLowRankUplift: out = z + U_l (V_l^T z), per-sample layer l.
// B=2048, H=2048, R=64, L=32.
//
// R11 (= R9 resubmit + minor tuning; R10 was an infra failure, no signal):
// de-fused 3-kernel design to fix latency-boundness (R8: occ 12.5%, all
// pipes <16% -> serialization). tf32 mma.sync math (validated in R8,
// rel_err 5.4e-5).
//  K1 setup:  group samples by layer into <=16-sample tiles (worklist).
//  K2 proj:   grid (tiles x SPLITK=8). Each CTA reduces a 256-wide H chunk:
//             g_proj[sp][b][r] partial = Z_chunk @ V_chunk.  ~1280 CTAs.
//  K3 uplift: grid (tiles x H/128). Each CTA: proj = sum partials (float2,
//             overlapped with U cp.async), then out[16x128] = z + proj @ U^T.
//             ~2560 CTAs.

#define T_SAMP   16
#define KT       64
#define RANK     64
#define L_CAP    64
#define B_CAP    4096
#define MAX_TILES 512
#define SPLITK   8
#define HB       128          // uplift h-block width

#define VSTRIDE  68
// proj-kernel stage float layout: V[64][68] at [0,4352), Z[16][68] at [4352,5440)
#define STAGE_F  5440

__device__ int g_order[B_CAP];
__device__ int g_tile_layer[MAX_TILES];
__device__ int g_tile_start[MAX_TILES];
__device__ int g_tile_cnt[MAX_TILES];
__device__ int g_num_tiles;
__device__ float g_proj[SPLITK][B_CAP][RANK];   // 8MB scratch (no atomics)

__device__ __forceinline__ void cp16(float* sdst, const float* gsrc) {
    unsigned s = (unsigned)__cvta_generic_to_shared(sdst);
    asm volatile("cp.async.cg.shared.global [%0], [%1], 16;" :: "r"(s), "l"(gsrc));
}
__device__ __forceinline__ void cp_commit() {
    asm volatile("cp.async.commit_group;");
}
__device__ __forceinline__ void cp_wait1() {
    asm volatile("cp.async.wait_group 1;");
}
__device__ __forceinline__ void cp_wait0() {
    asm volatile("cp.async.wait_group 0;");
}

// D += A(16x8, row) * B(8x8, col), tf32 inputs taken as raw fp32 bits.
__device__ __forceinline__ void mma_tf32(float* c,
                                         float a0, float a1, float a2, float a3,
                                         float b0, float b1)
{
    uint32_t ua0 = __float_as_uint(a0), ua1 = __float_as_uint(a1);
    uint32_t ua2 = __float_as_uint(a2), ua3 = __float_as_uint(a3);
    uint32_t ub0 = __float_as_uint(b0), ub1 = __float_as_uint(b1);
    asm volatile(
        "mma.sync.aligned.m16n8k8.row.col.f32.tf32.tf32.f32 "
        "{%0,%1,%2,%3}, {%4,%5,%6,%7}, {%8,%9}, {%0,%1,%2,%3};\n"
        : "+f"(c[0]), "+f"(c[1]), "+f"(c[2]), "+f"(c[3])
        : "r"(ua0), "r"(ua1), "r"(ua2), "r"(ua3), "r"(ub0), "r"(ub1));
}

// ---------------------------------------------------------------------------
// K1 setup: histogram layer_ids, prefix-sum, scatter into layer-sorted order,
// emit worklist of (layer, start, count<=16) tiles. Single CTA.
// ---------------------------------------------------------------------------
__global__ void llru_setup_kernel(const int* __restrict__ lids, int B, int L)
{
    __shared__ int cnt[L_CAP];
    __shared__ int cur[L_CAP];
    int tid = threadIdx.x;

    for (int i = tid; i < L_CAP; i += blockDim.x) cnt[i] = 0;
    __syncthreads();

    for (int b = tid; b < B; b += blockDim.x)
        atomicAdd(&cnt[lids[b]], 1);
    __syncthreads();

    if (tid == 0) {
        int acc = 0;
        int nt = 0;
        for (int l = 0; l < L; l++) {
            cur[l] = acc;
            int c = cnt[l];
            for (int t = 0; t < c; t += T_SAMP) {
                g_tile_layer[nt] = l;
                g_tile_start[nt] = acc + t;
                g_tile_cnt[nt]   = min(T_SAMP, c - t);
                nt++;
            }
            acc += c;
        }
        g_num_tiles = nt;
    }
    __syncthreads();

    for (int b = tid; b < B; b += blockDim.x) {
        int p = atomicAdd(&cur[lids[b]], 1);
        g_order[p] = b;
    }
}

// ---------------------------------------------------------------------------
// K2 proj: CTA = (tile g, split sp). Reduce H-chunk [sp*H/8, (sp+1)*H/8)
// into g_proj[sp][b][r]. 256 threads / 8 warps; warp w owns r-block [8w,8w+8).
// cp.async double-buffered over the chunk's 4 k-tiles.
// ---------------------------------------------------------------------------
__global__ void __launch_bounds__(256)
llru_proj_kernel(const float* __restrict__ z,
                 const float* __restrict__ v,
                 int H)
{
    int g = blockIdx.x;
    if (g >= g_num_tiles) return;
    const int sp = blockIdx.y;

    const int layer = g_tile_layer[g];
    const int start = g_tile_start[g];
    const int cnt   = g_tile_cnt[g];

    const int tid  = threadIdx.x;
    const int lane = tid & 31;
    const int warp = tid >> 5;
    const int qr   = lane >> 2;
    const int qc   = lane & 3;

    __shared__ int sid[T_SAMP];
    __shared__ __align__(16) float stage[2][STAGE_F];    // 43520 B

    if (tid < T_SAMP)
        sid[tid] = (tid < cnt) ? g_order[start + tid] : g_order[start];
    __syncthreads();

    const float* vL = v + (size_t)layer * H * RANK;

    const int hchunk = H / SPLITK;           // 256
    const int nkt    = hchunk / KT;          // 4
    const int kbase  = sp * hchunk;

    const int srow = tid >> 4;
    const int zc4  = (tid & 15) << 2;
    const float* zrow = z + (size_t)sid[srow] * H + zc4 + kbase;

    auto issue_tile = [&](int t) {
        float* buf = stage[t & 1];
        int k0 = kbase + t * KT;
        #pragma unroll
        for (int j = 0; j < 4; j++) {
            int idx  = tid + j * 256;
            int krow = idx >> 4;
            int c4   = (idx & 15) << 2;
            cp16(buf + krow * VSTRIDE + c4,
                 vL + (size_t)(k0 + krow) * RANK + c4);
        }
        cp16(buf + 4352 + srow * VSTRIDE + zc4, zrow + t * KT);
        cp_commit();
    };

    issue_tile(0);
    issue_tile(1);

    float accA[4] = {0.f, 0.f, 0.f, 0.f};
    float accB[4] = {0.f, 0.f, 0.f, 0.f};

    for (int t = 0; t < nkt; t++) {
        cp_wait1();
        __syncthreads();

        const float* Vb = stage[t & 1];
        const float* Zb = Vb + 4352;
        #pragma unroll
        for (int s = 0; s < 8; s++) {
            int k0 = s * 8;
            float a0 = Zb[qr * VSTRIDE + k0 + qc];
            float a1 = Zb[(qr + 8) * VSTRIDE + k0 + qc];
            float a2 = Zb[qr * VSTRIDE + k0 + qc + 4];
            float a3 = Zb[(qr + 8) * VSTRIDE + k0 + qc + 4];
            float b0 = Vb[(k0 + qc) * VSTRIDE + warp * 8 + qr];
            float b1 = Vb[(k0 + qc + 4) * VSTRIDE + warp * 8 + qr];
            if (s & 1) mma_tf32(accB, a0, a1, a2, a3, b0, b1);
            else       mma_tf32(accA, a0, a1, a2, a3, b0, b1);
        }

        __syncthreads();
        if (t + 2 < nkt) issue_tile(t + 2);
        else             cp_commit();        // keep wait_group(1) exact
    }

    // publish partial proj: D frag rows qr, qr+8; cols warp*8 + 2qc + {0,1}
    int nb = warp * 8 + 2 * qc;
    if (qr < cnt) {
        float2 p0 = make_float2(accA[0] + accB[0], accA[1] + accB[1]);
        *(float2*)&g_proj[sp][sid[qr]][nb] = p0;
    }
    if (qr + 8 < cnt) {
        float2 p1 = make_float2(accA[2] + accB[2], accA[3] + accB[3]);
        *(float2*)&g_proj[sp][sid[qr + 8]][nb] = p1;
    }
}

// ---------------------------------------------------------------------------
// K3 uplift: CTA = (tile g, h-block hb). out[16 x 128] = z + proj @ U^T.
// Prologue sums the SPLITK proj partials (float2, overlapped with the U
// chunk cp.async). Warp w owns h-cols [hb*128 + w*16, +16).
// ---------------------------------------------------------------------------
__global__ void __launch_bounds__(256)
llru_uplift_kernel(const float* __restrict__ z,
                   const float* __restrict__ u,
                   float* __restrict__ out,
                   int H)
{
    int g = blockIdx.x;
    if (g >= g_num_tiles) return;
    const int h0 = blockIdx.y * HB;

    const int layer = g_tile_layer[g];
    const int start = g_tile_start[g];
    const int cnt   = g_tile_cnt[g];

    const int tid  = threadIdx.x;
    const int lane = tid & 31;
    const int warp = tid >> 5;
    const int qr   = lane >> 2;
    const int qc   = lane & 3;

    __shared__ int sid[T_SAMP];
    __shared__ __align__(16) float Us[HB][VSTRIDE];          // 34816 B
    __shared__ __align__(16) float projS[T_SAMP][VSTRIDE];   //  4352 B

    if (tid < T_SAMP)
        sid[tid] = (tid < cnt) ? g_order[start + tid] : g_order[start];
    __syncthreads();

    // issue U chunk load first (latency overlapped with proj reduction)
    const float* uL = u + (size_t)layer * H * RANK;
    #pragma unroll
    for (int j = 0; j < 8; j++) {
        int idx  = tid + j * 256;          // 0..2047
        int hrow = idx >> 4;
        int c4   = (idx & 15) << 2;
        cp16(&Us[hrow][c4], uL + (size_t)(h0 + hrow) * RANK + c4);
    }
    cp_commit();

    // reduce proj partials while U streams in (float2 granularity)
    #pragma unroll
    for (int i = tid; i < T_SAMP * (RANK / 2); i += 256) {
        int s  = i >> 5;              // sample 0..15
        int r2 = (i & 31) << 1;       // even rank index
        int b  = sid[s];
        float2 acc = make_float2(0.f, 0.f);
        #pragma unroll
        for (int p = 0; p < SPLITK; p++) {
            float2 pp = *(const float2*)&g_proj[p][b][r2];
            acc.x += pp.x;
            acc.y += pp.y;
        }
        *(float2*)&projS[s][r2] = acc;
    }

    cp_wait0();
    __syncthreads();

    // proj A-fragments (k = rank, 8 steps of k8)
    float pa[8][4];
    #pragma unroll
    for (int s = 0; s < 8; s++) {
        int k0 = s * 8;
        pa[s][0] = projS[qr][k0 + qc];
        pa[s][1] = projS[qr + 8][k0 + qc];
        pa[s][2] = projS[qr][k0 + qc + 4];
        pa[s][3] = projS[qr + 8][k0 + qc + 4];
    }

    #pragma unroll
    for (int nb = 0; nb < 2; nb++) {
        const int hloc = warp * 16 + nb * 8;        // local n-block base
        float acc[4] = {0.f, 0.f, 0.f, 0.f};
        #pragma unroll
        for (int s = 0; s < 8; s++) {
            int k0 = s * 8;
            float b0 = Us[hloc + qr][k0 + qc];
            float b1 = Us[hloc + qr][k0 + qc + 4];
            mma_tf32(acc, pa[s][0], pa[s][1], pa[s][2], pa[s][3], b0, b1);
        }
        int colbase = h0 + hloc + 2 * qc;
        if (qr < cnt) {
            size_t gidx = (size_t)sid[qr] * H + colbase;
            float2 zz = *(const float2*)(z + gidx);
            *(float2*)(out + gidx) = make_float2(zz.x + acc[0], zz.y + acc[1]);
        }
        if (qr + 8 < cnt) {
            size_t gidx = (size_t)sid[qr + 8] * H + colbase;
            float2 zz = *(const float2*)(z + gidx);
            *(float2*)(out + gidx) = make_float2(zz.x + acc[2], zz.y + acc[3]);
        }
    }
}

extern "C" void kernel_launch(void* const* d_in, const int* in_sizes, int n_in,
                              void* d_out, int out_size)
{
    const float* z    = (const float*)d_in[0];
    const int*   lids = (const int*)d_in[1];
    const float* u    = (const float*)d_in[2];
    const float* v    = (const float*)d_in[3];
    float*       out  = (float*)d_out;

    int B = in_sizes[1];
    int H = in_sizes[0] / B;
    int L = in_sizes[2] / (H * RANK);
    if (L < 1) L = 1;
    if (L > L_CAP) L = L_CAP;

    llru_setup_kernel<<<1, 256>>>(lids, B, L);

    int ntiles = B / T_SAMP + L;       // upper bound on emitted tiles
    if (ntiles > MAX_TILES) ntiles = MAX_TILES;

    dim3 gridA(ntiles, SPLITK);
    llru_proj_kernel<<<gridA, 256>>>(z, v, H);

    dim3 gridB(ntiles, H / HB);
    llru_uplift_kernel<<<gridB, 256>>>(z, u, out, H);
}

// round 12
// speedup vs baseline: 2.2573x; 1.1404x over previous
#include <cuda_runtime.h>
#include <cstdint>

// LayerwiseLowRankUplift: out = z + U_l (V_l^T z), per-sample layer l.
// B=2048, H=2048, R=64, L=32.
//
// R12: R11 (de-fused, tf32 mma, 49.9us) +
//  (a) parallelized setup kernel (was 12.8us of serial tid==0 emission),
//  (b) T_SAMP 16->32: halves (u,v) weight traffic (~190MB -> ~105MB).
//  K1 setup:  group samples by layer into <=32-sample tiles (worklist).
//  K2 proj:   grid (tiles x SPLITK=8); CTA reduces a 256-wide H chunk
//             (8 k-tiles of 32) into g_proj[sp][b][r].
//  K3 uplift: grid (tiles x H/128); CTA: proj = sum partials, then
//             out[32 x 128 cols] = z + proj @ U_chunk^T.

#define T_SAMP   32
#define KT       32            // K2 k-tile rows
#define RANK     64
#define L_CAP    64
#define B_CAP    4096
#define MAX_TILES 512
#define SPLITK   8
#define HB       128           // K3 h-block width

#define VSTRIDE  68            // 64-float rows padded (U/V tiles, projS)
#define ZSTRIDE  36            // 32-float rows padded (K2 Z tile)
// K2 stage float layout: V[32][68] at [0,2176), Z[32][36] at [2176,3328)
#define STAGE_F  3328

__device__ int g_order[B_CAP];
__device__ int g_tile_layer[MAX_TILES];
__device__ int g_tile_start[MAX_TILES];
__device__ int g_tile_cnt[MAX_TILES];
__device__ int g_num_tiles;
__device__ float g_proj[SPLITK][B_CAP][RANK];   // 8MB scratch (no atomics)

__device__ __forceinline__ void cp16(float* sdst, const float* gsrc) {
    unsigned s = (unsigned)__cvta_generic_to_shared(sdst);
    asm volatile("cp.async.cg.shared.global [%0], [%1], 16;" :: "r"(s), "l"(gsrc));
}
__device__ __forceinline__ void cp_commit() {
    asm volatile("cp.async.commit_group;");
}
__device__ __forceinline__ void cp_wait1() {
    asm volatile("cp.async.wait_group 1;");
}
__device__ __forceinline__ void cp_wait0() {
    asm volatile("cp.async.wait_group 0;");
}

// D += A(16x8, row) * B(8x8, col), tf32 inputs taken as raw fp32 bits.
__device__ __forceinline__ void mma_tf32(float* c,
                                         float a0, float a1, float a2, float a3,
                                         float b0, float b1)
{
    uint32_t ua0 = __float_as_uint(a0), ua1 = __float_as_uint(a1);
    uint32_t ua2 = __float_as_uint(a2), ua3 = __float_as_uint(a3);
    uint32_t ub0 = __float_as_uint(b0), ub1 = __float_as_uint(b1);
    asm volatile(
        "mma.sync.aligned.m16n8k8.row.col.f32.tf32.tf32.f32 "
        "{%0,%1,%2,%3}, {%4,%5,%6,%7}, {%8,%9}, {%0,%1,%2,%3};\n"
        : "+f"(c[0]), "+f"(c[1]), "+f"(c[2]), "+f"(c[3])
        : "r"(ua0), "r"(ua1), "r"(ua2), "r"(ua3), "r"(ub0), "r"(ub1));
}

// ---------------------------------------------------------------------------
// K1 setup (parallelized): histogram -> scan (32 smem iters, tid 0) ->
// PARALLEL tile emission (one thread per layer) -> parallel scatter using a
// separate cursor array (no race with emission's read of the layer starts).
// ---------------------------------------------------------------------------
__global__ void llru_setup_kernel(const int* __restrict__ lids, int B, int L)
{
    __shared__ int cnt[L_CAP];
    __shared__ int lstart[L_CAP];   // first sorted slot of layer l
    __shared__ int tbase[L_CAP];    // first tile index of layer l
    __shared__ int scur[L_CAP];     // scatter cursor
    int tid = threadIdx.x;

    for (int i = tid; i < L_CAP; i += blockDim.x) cnt[i] = 0;
    __syncthreads();

    for (int b = tid; b < B; b += blockDim.x)
        atomicAdd(&cnt[lids[b]], 1);
    __syncthreads();

    if (tid == 0) {
        int acc = 0, nt = 0;
        for (int l = 0; l < L; l++) {
            lstart[l] = acc;
            tbase[l]  = nt;
            nt  += (cnt[l] + T_SAMP - 1) / T_SAMP;
            acc += cnt[l];
        }
        g_num_tiles = nt;
    }
    __syncthreads();

    if (tid < L) scur[tid] = lstart[tid];
    // parallel tile emission: one thread per layer (~4 tiles each)
    if (tid < L) {
        int l = tid, base = tbase[l], st = lstart[l], c = cnt[l];
        for (int j = 0; j * T_SAMP < c; j++) {
            g_tile_layer[base + j] = l;
            g_tile_start[base + j] = st + j * T_SAMP;
            g_tile_cnt[base + j]   = min(T_SAMP, c - j * T_SAMP);
        }
    }
    __syncthreads();

    for (int b = tid; b < B; b += blockDim.x) {
        int p = atomicAdd(&scur[lids[b]], 1);
        g_order[p] = b;
    }
}

// ---------------------------------------------------------------------------
// K2 proj: CTA = (tile g, split sp). Reduce H-chunk [sp*256, (sp+1)*256)
// into g_proj[sp][b][r] for the tile's <=32 samples.
// 256 threads / 8 warps as 2(m) x 4(n): warp owns 16 m-rows x 16 n-cols.
// cp.async double-buffered over 8 k-tiles of 32 rows.
// ---------------------------------------------------------------------------
__global__ void __launch_bounds__(256)
llru_proj_kernel(const float* __restrict__ z,
                 const float* __restrict__ v,
                 int H)
{
    int g = blockIdx.x;
    if (g >= g_num_tiles) return;
    const int sp = blockIdx.y;

    const int layer = g_tile_layer[g];
    const int start = g_tile_start[g];
    const int cnt   = g_tile_cnt[g];

    const int tid  = threadIdx.x;
    const int lane = tid & 31;
    const int warp = tid >> 5;
    const int wm   = warp >> 2;         // 0..1 : m-block (16 rows)
    const int wn   = warp & 3;          // 0..3 : n-block (16 cols)
    const int qr   = lane >> 2;
    const int qc   = lane & 3;

    __shared__ int sid[T_SAMP];
    __shared__ __align__(16) float stage[2][STAGE_F];    // 26624 B

    if (tid < T_SAMP)
        sid[tid] = (tid < cnt) ? g_order[start + tid] : g_order[start];
    __syncthreads();

    const float* vL = v + (size_t)layer * H * RANK;

    const int hchunk = H / SPLITK;            // 256
    const int nkt    = hchunk / KT;           // 8
    const int kbase  = sp * hchunk;

    // z cp.async coords: 1024 floats = 256 float4, 1 per thread
    const int zrow16 = tid >> 3;              // 0..31
    const int zc4    = (tid & 7) << 2;        // 0..28
    const float* zrow = z + (size_t)sid[zrow16] * H + kbase + zc4;

    auto issue_tile = [&](int t) {
        float* buf = stage[t & 1];
        int k0 = kbase + t * KT;
        // V: 32x64 = 512 float4, 2 per thread
        #pragma unroll
        for (int j = 0; j < 2; j++) {
            int idx  = tid + j * 256;
            int krow = idx >> 4;
            int c4   = (idx & 15) << 2;
            cp16(buf + krow * VSTRIDE + c4,
                 vL + (size_t)(k0 + krow) * RANK + c4);
        }
        cp16(buf + 2176 + zrow16 * ZSTRIDE + zc4, zrow + t * KT);
        cp_commit();
    };

    issue_tile(0);
    issue_tile(1);

    float acc[2][4] = {{0.f,0.f,0.f,0.f},{0.f,0.f,0.f,0.f}};  // per n-block

    for (int t = 0; t < nkt; t++) {
        cp_wait1();
        __syncthreads();

        const float* Vb = stage[t & 1];
        const float* Zb = Vb + 2176;
        const int m0 = wm * 16;
        #pragma unroll
        for (int s = 0; s < 4; s++) {         // 4 k-steps of 8
            int k0 = s * 8;
            float a0 = Zb[(m0 + qr) * ZSTRIDE + k0 + qc];
            float a1 = Zb[(m0 + qr + 8) * ZSTRIDE + k0 + qc];
            float a2 = Zb[(m0 + qr) * ZSTRIDE + k0 + qc + 4];
            float a3 = Zb[(m0 + qr + 8) * ZSTRIDE + k0 + qc + 4];
            #pragma unroll
            for (int nb = 0; nb < 2; nb++) {
                int nbase = wn * 16 + nb * 8;
                float b0 = Vb[(k0 + qc) * VSTRIDE + nbase + qr];
                float b1 = Vb[(k0 + qc + 4) * VSTRIDE + nbase + qr];
                mma_tf32(acc[nb], a0, a1, a2, a3, b0, b1);
            }
        }

        __syncthreads();
        if (t + 2 < nkt) issue_tile(t + 2);
        else             cp_commit();         // keep wait_group(1) exact
    }

    // publish partials: D frag rows m0+qr, m0+qr+8; cols nbase + 2qc + {0,1}
    const int m0 = wm * 16;
    #pragma unroll
    for (int nb = 0; nb < 2; nb++) {
        int col = wn * 16 + nb * 8 + 2 * qc;
        if (m0 + qr < cnt)
            *(float2*)&g_proj[sp][sid[m0 + qr]][col] =
                make_float2(acc[nb][0], acc[nb][1]);
        if (m0 + qr + 8 < cnt)
            *(float2*)&g_proj[sp][sid[m0 + qr + 8]][col] =
                make_float2(acc[nb][2], acc[nb][3]);
    }
}

// ---------------------------------------------------------------------------
// K3 uplift: CTA = (tile g, h-block hb). out[32 x 128] = z + proj @ U^T.
// Prologue sums SPLITK proj partials (overlapped with U cp.async).
// Warp w owns h-cols [h0 + w*16, +16); loops 2 m-blocks x 2 n-blocks.
// ---------------------------------------------------------------------------
__global__ void __launch_bounds__(256)
llru_uplift_kernel(const float* __restrict__ z,
                   const float* __restrict__ u,
                   float* __restrict__ out,
                   int H)
{
    int g = blockIdx.x;
    if (g >= g_num_tiles) return;
    const int h0 = blockIdx.y * HB;

    const int layer = g_tile_layer[g];
    const int start = g_tile_start[g];
    const int cnt   = g_tile_cnt[g];

    const int tid  = threadIdx.x;
    const int lane = tid & 31;
    const int warp = tid >> 5;
    const int qr   = lane >> 2;
    const int qc   = lane & 3;

    __shared__ int sid[T_SAMP];
    __shared__ __align__(16) float Us[HB][VSTRIDE];          // 34816 B
    __shared__ __align__(16) float projS[T_SAMP][VSTRIDE];   //  8704 B

    if (tid < T_SAMP)
        sid[tid] = (tid < cnt) ? g_order[start + tid] : g_order[start];
    __syncthreads();

    // U chunk cp.async first (latency overlapped with proj reduction)
    const float* uL = u + (size_t)layer * H * RANK;
    #pragma unroll
    for (int j = 0; j < 8; j++) {
        int idx  = tid + j * 256;          // 0..2047
        int hrow = idx >> 4;
        int c4   = (idx & 15) << 2;
        cp16(&Us[hrow][c4], uL + (size_t)(h0 + hrow) * RANK + c4);
    }
    cp_commit();

    // reduce proj partials while U streams in (float2 granularity)
    #pragma unroll
    for (int i = tid; i < T_SAMP * (RANK / 2); i += 256) {
        int s  = i >> 5;              // sample 0..31
        int r2 = (i & 31) << 1;       // even rank index
        int b  = sid[s];
        float2 a = make_float2(0.f, 0.f);
        #pragma unroll
        for (int p = 0; p < SPLITK; p++) {
            float2 pp = *(const float2*)&g_proj[p][b][r2];
            a.x += pp.x;
            a.y += pp.y;
        }
        *(float2*)&projS[s][r2] = a;
    }

    cp_wait0();
    __syncthreads();

    #pragma unroll
    for (int mb = 0; mb < 2; mb++) {
        const int m0 = mb * 16;
        // A fragments for this m-block (k = rank, 8 steps of k8)
        float pa[8][4];
        #pragma unroll
        for (int s = 0; s < 8; s++) {
            int k0 = s * 8;
            pa[s][0] = projS[m0 + qr][k0 + qc];
            pa[s][1] = projS[m0 + qr + 8][k0 + qc];
            pa[s][2] = projS[m0 + qr][k0 + qc + 4];
            pa[s][3] = projS[m0 + qr + 8][k0 + qc + 4];
        }
        #pragma unroll
        for (int nb = 0; nb < 2; nb++) {
            const int hloc = warp * 16 + nb * 8;
            float acc[4] = {0.f, 0.f, 0.f, 0.f};
            #pragma unroll
            for (int s = 0; s < 8; s++) {
                int k0 = s * 8;
                float b0 = Us[hloc + qr][k0 + qc];
                float b1 = Us[hloc + qr][k0 + qc + 4];
                mma_tf32(acc, pa[s][0], pa[s][1], pa[s][2], pa[s][3], b0, b1);
            }
            int colbase = h0 + hloc + 2 * qc;
            if (m0 + qr < cnt) {
                size_t gidx = (size_t)sid[m0 + qr] * H + colbase;
                float2 zz = *(const float2*)(z + gidx);
                *(float2*)(out + gidx) = make_float2(zz.x + acc[0], zz.y + acc[1]);
            }
            if (m0 + qr + 8 < cnt) {
                size_t gidx = (size_t)sid[m0 + qr + 8] * H + colbase;
                float2 zz = *(const float2*)(z + gidx);
                *(float2*)(out + gidx) = make_float2(zz.x + acc[2], zz.y + acc[3]);
            }
        }
    }
}

extern "C" void kernel_launch(void* const* d_in, const int* in_sizes, int n_in,
                              void* d_out, int out_size)
{
    const float* z    = (const float*)d_in[0];
    const int*   lids = (const int*)d_in[1];
    const float* u    = (const float*)d_in[2];
    const float* v    = (const float*)d_in[3];
    float*       out  = (float*)d_out;

    int B = in_sizes[1];
    int H = in_sizes[0] / B;
    int L = in_sizes[2] / (H * RANK);
    if (L < 1) L = 1;
    if (L > L_CAP) L = L_CAP;

    llru_setup_kernel<<<1, 256>>>(lids, B, L);

    int ntiles = B / T_SAMP + L;       // upper bound on emitted tiles
    if (ntiles > MAX_TILES) ntiles = MAX_TILES;

    dim3 gridA(ntiles, SPLITK);
    llru_proj_kernel<<<gridA, 256>>>(z, v, H);

    dim3 gridB(ntiles, H / HB);
    llru_uplift_kernel<<<gridB, 256>>>(z, u, out, H);
}

// round 14
// speedup vs baseline: 2.4125x; 1.0688x over previous
#include <cuda_runtime.h>
#include <cstdint>

// LayerwiseLowRankUplift: out = z + U_l (V_l^T z), per-sample layer l.
// B=2048, H=2048, R=64, L=32.
//
// R13: R12 (43.8us) +
//  (a) setup: single pass over lids cached in registers (was 2 latency-bound
//      passes; 10.2us -> ~3us predicted),
//  (b) new K2.5 reduce kernel: g_proj[8][b][r] -> g_projf[b][r] once,
//      removing the 8-way redundant partial reduction from all 16 K3 h-blocks
//      (~70MB L2 -> ~12MB) and its 8-deep dependent-load chain,
//  (c) K3 prologue fully async (proj + U in one cp.async group).

#define T_SAMP   32
#define KT       32            // K2 k-tile rows
#define RANK     64
#define L_CAP    64
#define B_CAP    4096
#define MAX_TILES 512
#define SPLITK   8
#define HB       128           // K3 h-block width

#define VSTRIDE  68            // 64-float rows padded (U/V tiles, projS)
#define ZSTRIDE  36            // 32-float rows padded (K2 Z tile)
// K2 stage float layout: V[32][68] at [0,2176), Z[32][36] at [2176,3328)
#define STAGE_F  3328

__device__ int g_order[B_CAP];
__device__ int g_tile_layer[MAX_TILES];
__device__ int g_tile_start[MAX_TILES];
__device__ int g_tile_cnt[MAX_TILES];
__device__ int g_num_tiles;
__device__ float g_proj[SPLITK][B_CAP][RANK];   // 8MB scratch (no atomics)
__device__ float g_projf[B_CAP][RANK];          // 1MB final proj

__device__ __forceinline__ void cp16(float* sdst, const float* gsrc) {
    unsigned s = (unsigned)__cvta_generic_to_shared(sdst);
    asm volatile("cp.async.cg.shared.global [%0], [%1], 16;" :: "r"(s), "l"(gsrc));
}
__device__ __forceinline__ void cp_commit() {
    asm volatile("cp.async.commit_group;");
}
__device__ __forceinline__ void cp_wait1() {
    asm volatile("cp.async.wait_group 1;");
}
__device__ __forceinline__ void cp_wait0() {
    asm volatile("cp.async.wait_group 0;");
}

// D += A(16x8, row) * B(8x8, col), tf32 inputs taken as raw fp32 bits.
__device__ __forceinline__ void mma_tf32(float* c,
                                         float a0, float a1, float a2, float a3,
                                         float b0, float b1)
{
    uint32_t ua0 = __float_as_uint(a0), ua1 = __float_as_uint(a1);
    uint32_t ua2 = __float_as_uint(a2), ua3 = __float_as_uint(a3);
    uint32_t ub0 = __float_as_uint(b0), ub1 = __float_as_uint(b1);
    asm volatile(
        "mma.sync.aligned.m16n8k8.row.col.f32.tf32.tf32.f32 "
        "{%0,%1,%2,%3}, {%4,%5,%6,%7}, {%8,%9}, {%0,%1,%2,%3};\n"
        : "+f"(c[0]), "+f"(c[1]), "+f"(c[2]), "+f"(c[3])
        : "r"(ua0), "r"(ua1), "r"(ua2), "r"(ua3), "r"(ub0), "r"(ub1));
}

// ---------------------------------------------------------------------------
// K1 setup: 1024 threads. lids is read ONCE into registers (batched LDGs ->
// one exposed latency), reused for histogram and scatter. Serial work is only
// the 32-layer scan on tid 0; tile emission is one thread per layer.
// ---------------------------------------------------------------------------
__global__ void __launch_bounds__(1024)
llru_setup_kernel(const int* __restrict__ lids, int B, int L)
{
    __shared__ int cnt[L_CAP];
    __shared__ int lstart[L_CAP];   // first sorted slot of layer l
    __shared__ int tbase[L_CAP];    // first tile index of layer l
    __shared__ int scur[L_CAP];     // scatter cursor
    int tid = threadIdx.x;

    // cache this thread's lids values (<= 4 at B_CAP=4096)
    int myl[4], myb[4], n = 0;
    #pragma unroll
    for (int j = 0; j < 4; j++) {
        int b = tid + j * 1024;
        if (b < B) { myb[n] = b; myl[n] = lids[b]; n++; }
    }

    for (int i = tid; i < L_CAP; i += 1024) cnt[i] = 0;
    __syncthreads();

    for (int j = 0; j < n; j++)
        atomicAdd(&cnt[myl[j]], 1);
    __syncthreads();

    if (tid == 0) {
        int acc = 0, nt = 0;
        for (int l = 0; l < L; l++) {
            lstart[l] = acc;
            tbase[l]  = nt;
            nt  += (cnt[l] + T_SAMP - 1) / T_SAMP;
            acc += cnt[l];
        }
        g_num_tiles = nt;
    }
    __syncthreads();

    if (tid < L) {
        int l = tid, base = tbase[l], st = lstart[l], c = cnt[l];
        scur[l] = st;
        for (int j = 0; j * T_SAMP < c; j++) {
            g_tile_layer[base + j] = l;
            g_tile_start[base + j] = st + j * T_SAMP;
            g_tile_cnt[base + j]   = min(T_SAMP, c - j * T_SAMP);
        }
    }
    __syncthreads();

    for (int j = 0; j < n; j++) {
        int p = atomicAdd(&scur[myl[j]], 1);
        g_order[p] = myb[j];
    }
}

// ---------------------------------------------------------------------------
// K2 proj: CTA = (tile g, split sp). Reduce H-chunk [sp*256, (sp+1)*256)
// into g_proj[sp][b][r] for the tile's <=32 samples.
// 256 threads / 8 warps as 2(m) x 4(n). cp.async double-buffered, 8 k-tiles.
// ---------------------------------------------------------------------------
__global__ void __launch_bounds__(256)
llru_proj_kernel(const float* __restrict__ z,
                 const float* __restrict__ v,
                 int H)
{
    int g = blockIdx.x;
    if (g >= g_num_tiles) return;
    const int sp = blockIdx.y;

    const int layer = g_tile_layer[g];
    const int start = g_tile_start[g];
    const int cnt   = g_tile_cnt[g];

    const int tid  = threadIdx.x;
    const int lane = tid & 31;
    const int warp = tid >> 5;
    const int wm   = warp >> 2;         // 0..1 : m-block (16 rows)
    const int wn   = warp & 3;          // 0..3 : n-block (16 cols)
    const int qr   = lane >> 2;
    const int qc   = lane & 3;

    __shared__ int sid[T_SAMP];
    __shared__ __align__(16) float stage[2][STAGE_F];    // 26624 B

    if (tid < T_SAMP)
        sid[tid] = (tid < cnt) ? g_order[start + tid] : g_order[start];
    __syncthreads();

    const float* vL = v + (size_t)layer * H * RANK;

    const int hchunk = H / SPLITK;            // 256
    const int nkt    = hchunk / KT;           // 8
    const int kbase  = sp * hchunk;

    // z cp.async coords: 1024 floats = 256 float4, 1 per thread
    const int zrow16 = tid >> 3;              // 0..31
    const int zc4    = (tid & 7) << 2;        // 0..28
    const float* zrow = z + (size_t)sid[zrow16] * H + kbase + zc4;

    auto issue_tile = [&](int t) {
        float* buf = stage[t & 1];
        int k0 = kbase + t * KT;
        // V: 32x64 = 512 float4, 2 per thread
        #pragma unroll
        for (int j = 0; j < 2; j++) {
            int idx  = tid + j * 256;
            int krow = idx >> 4;
            int c4   = (idx & 15) << 2;
            cp16(buf + krow * VSTRIDE + c4,
                 vL + (size_t)(k0 + krow) * RANK + c4);
        }
        cp16(buf + 2176 + zrow16 * ZSTRIDE + zc4, zrow + t * KT);
        cp_commit();
    };

    issue_tile(0);
    issue_tile(1);

    float acc[2][4] = {{0.f,0.f,0.f,0.f},{0.f,0.f,0.f,0.f}};  // per n-block

    for (int t = 0; t < nkt; t++) {
        cp_wait1();
        __syncthreads();

        const float* Vb = stage[t & 1];
        const float* Zb = Vb + 2176;
        const int m0 = wm * 16;
        #pragma unroll
        for (int s = 0; s < 4; s++) {         // 4 k-steps of 8
            int k0 = s * 8;
            float a0 = Zb[(m0 + qr) * ZSTRIDE + k0 + qc];
            float a1 = Zb[(m0 + qr + 8) * ZSTRIDE + k0 + qc];
            float a2 = Zb[(m0 + qr) * ZSTRIDE + k0 + qc + 4];
            float a3 = Zb[(m0 + qr + 8) * ZSTRIDE + k0 + qc + 4];
            #pragma unroll
            for (int nb = 0; nb < 2; nb++) {
                int nbase = wn * 16 + nb * 8;
                float b0 = Vb[(k0 + qc) * VSTRIDE + nbase + qr];
                float b1 = Vb[(k0 + qc + 4) * VSTRIDE + nbase + qr];
                mma_tf32(acc[nb], a0, a1, a2, a3, b0, b1);
            }
        }

        __syncthreads();
        if (t + 2 < nkt) issue_tile(t + 2);
        else             cp_commit();         // keep wait_group(1) exact
    }

    // publish partials: D frag rows m0+qr, m0+qr+8; cols nbase + 2qc + {0,1}
    const int m0 = wm * 16;
    #pragma unroll
    for (int nb = 0; nb < 2; nb++) {
        int col = wn * 16 + nb * 8 + 2 * qc;
        if (m0 + qr < cnt)
            *(float2*)&g_proj[sp][sid[m0 + qr]][col] =
                make_float2(acc[nb][0], acc[nb][1]);
        if (m0 + qr + 8 < cnt)
            *(float2*)&g_proj[sp][sid[m0 + qr + 8]][col] =
                make_float2(acc[nb][2], acc[nb][3]);
    }
}

// ---------------------------------------------------------------------------
// K2.5 reduce: g_projf[b][r] = sum_p g_proj[p][b][r]. Flat float2 grid.
// ---------------------------------------------------------------------------
__global__ void __launch_bounds__(256)
llru_reduce_kernel(int B)
{
    int i = blockIdx.x * 256 + threadIdx.x;     // float2 index
    int ntot = B * (RANK / 2);
    if (i >= ntot) return;

    float2 a = make_float2(0.f, 0.f);
    #pragma unroll
    for (int p = 0; p < SPLITK; p++) {
        const float2* src = (const float2*)&g_proj[p][0][0];
        float2 pp = src[i];
        a.x += pp.x;
        a.y += pp.y;
    }
    ((float2*)&g_projf[0][0])[i] = a;
}

// ---------------------------------------------------------------------------
// K3 uplift: CTA = (tile g, h-block hb). out[32 x 128] = z + proj @ U^T.
// Prologue: one cp.async group loads U chunk AND final proj rows.
// Warp w owns h-cols [h0 + w*16, +16); loops 2 m-blocks x 2 n-blocks.
// ---------------------------------------------------------------------------
__global__ void __launch_bounds__(256)
llru_uplift_kernel(const float* __restrict__ z,
                   const float* __restrict__ u,
                   float* __restrict__ out,
                   int H)
{
    int g = blockIdx.x;
    if (g >= g_num_tiles) return;
    const int h0 = blockIdx.y * HB;

    const int layer = g_tile_layer[g];
    const int start = g_tile_start[g];
    const int cnt   = g_tile_cnt[g];

    const int tid  = threadIdx.x;
    const int lane = tid & 31;
    const int warp = tid >> 5;
    const int qr   = lane >> 2;
    const int qc   = lane & 3;

    __shared__ int sid[T_SAMP];
    __shared__ __align__(16) float Us[HB][VSTRIDE];          // 34816 B
    __shared__ __align__(16) float projS[T_SAMP][VSTRIDE];   //  8704 B

    if (tid < T_SAMP)
        sid[tid] = (tid < cnt) ? g_order[start + tid] : g_order[start];
    __syncthreads();

    // one async group: U chunk (8 cp16/thread) + final proj (<=1 cp16/thread)
    const float* uL = u + (size_t)layer * H * RANK;
    #pragma unroll
    for (int j = 0; j < 8; j++) {
        int idx  = tid + j * 256;          // 0..2047
        int hrow = idx >> 4;
        int c4   = (idx & 15) << 2;
        cp16(&Us[hrow][c4], uL + (size_t)(h0 + hrow) * RANK + c4);
    }
    if (tid < T_SAMP * (RANK / 16)) {      // 128 threads: 32 rows x 4 quads
        int s  = tid >> 2;
        int c4 = (tid & 3) << 4;           // 0,16,32,48
        cp16(&projS[s][c4], &g_projf[sid[s]][c4]);
        cp16(&projS[s][c4 + 4], &g_projf[sid[s]][c4 + 4]);
        cp16(&projS[s][c4 + 8], &g_projf[sid[s]][c4 + 8]);
        cp16(&projS[s][c4 + 12], &g_projf[sid[s]][c4 + 12]);
    }
    cp_commit();
    cp_wait0();
    __syncthreads();

    #pragma unroll
    for (int mb = 0; mb < 2; mb++) {
        const int m0 = mb * 16;
        // A fragments for this m-block (k = rank, 8 steps of k8)
        float pa[8][4];
        #pragma unroll
        for (int s = 0; s < 8; s++) {
            int k0 = s * 8;
            pa[s][0] = projS[m0 + qr][k0 + qc];
            pa[s][1] = projS[m0 + qr + 8][k0 + qc];
            pa[s][2] = projS[m0 + qr][k0 + qc + 4];
            pa[s][3] = projS[m0 + qr + 8][k0 + qc + 4];
        }
        #pragma unroll
        for (int nb = 0; nb < 2; nb++) {
            const int hloc = warp * 16 + nb * 8;
            float acc[4] = {0.f, 0.f, 0.f, 0.f};
            #pragma unroll
            for (int s = 0; s < 8; s++) {
                int k0 = s * 8;
                float b0 = Us[hloc + qr][k0 + qc];
                float b1 = Us[hloc + qr][k0 + qc + 4];
                mma_tf32(acc, pa[s][0], pa[s][1], pa[s][2], pa[s][3], b0, b1);
            }
            int colbase = h0 + hloc + 2 * qc;
            if (m0 + qr < cnt) {
                size_t gidx = (size_t)sid[m0 + qr] * H + colbase;
                float2 zz = *(const float2*)(z + gidx);
                *(float2*)(out + gidx) = make_float2(zz.x + acc[0], zz.y + acc[1]);
            }
            if (m0 + qr + 8 < cnt) {
                size_t gidx = (size_t)sid[m0 + qr + 8] * H + colbase;
                float2 zz = *(const float2*)(z + gidx);
                *(float2*)(out + gidx) = make_float2(zz.x + acc[2], zz.y + acc[3]);
            }
        }
    }
}

extern "C" void kernel_launch(void* const* d_in, const int* in_sizes, int n_in,
                              void* d_out, int out_size)
{
    const float* z    = (const float*)d_in[0];
    const int*   lids = (const int*)d_in[1];
    const float* u    = (const float*)d_in[2];
    const float* v    = (const float*)d_in[3];
    float*       out  = (float*)d_out;

    int B = in_sizes[1];
    int H = in_sizes[0] / B;
    int L = in_sizes[2] / (H * RANK);
    if (L < 1) L = 1;
    if (L > L_CAP) L = L_CAP;

    llru_setup_kernel<<<1, 1024>>>(lids, B, L);

    int ntiles = B / T_SAMP + L;       // upper bound on emitted tiles
    if (ntiles > MAX_TILES) ntiles = MAX_TILES;

    dim3 gridA(ntiles, SPLITK);
    llru_proj_kernel<<<gridA, 256>>>(z, v, H);

    int nred = (B * (RANK / 2) + 255) / 256;
    llru_reduce_kernel<<<nred, 256>>>(B);

    dim3 gridB(ntiles, H / HB);
    llru_uplift_kernel<<<gridB, 256>>>(z, u, out, H);
}